// round 1
// baseline (speedup 1.0000x reference)
#include <cuda_runtime.h>
#include <math.h>

#define BB 8
#define NN 2048
#define FF 128
#define NWRD (NN / 32)   // 64 bitmask words per row

// ---------------- scratch (device globals; no allocations allowed) ----------
__device__ float    g_c[FF];                 // c = W @ a_i
__device__ float    g_u[BB * NN];            // u = exp(X @ c)
__device__ float    g_w[BB * NN];            // w = A @ u
__device__ float    g_xpart[BB * 8 * FF];    // per-chunk partial sums of X
__device__ float    g_S[BB * FF];            // S = (sum_n X) @ W
__device__ unsigned g_bits[BB * NN * NWRD];  // A != 0 bitmask (4 MB)

// ---------------- k0: c[fi] = sum_o W[fi,o] * a[128+o] ----------------------
__global__ void k0_c(const float* __restrict__ W, const float* __restrict__ a)
{
    __shared__ float sa[FF];
    int t = threadIdx.x;
    sa[t] = a[FF + t];            // a_i = a[0, 128:256]
    __syncthreads();
    const float* wr = W + t * FF;
    float s = 0.f;
#pragma unroll 8
    for (int o = 0; o < FF; o++) s += wr[o] * sa[o];
    g_c[t] = s;
}

// ---------------- k1: u = exp(X @ c); partial column-sums of X --------------
// grid (8 chunks, 8 batches), block 256 (8 warps, 32 rows each)
__global__ void k1_u_xsum(const float* __restrict__ X)
{
    const int b     = blockIdx.y;
    const int chunk = blockIdx.x;
    const int warp  = threadIdx.x >> 5;
    const int lane  = threadIdx.x & 31;

    __shared__ float sc[FF];
    __shared__ float sx[8][FF];
    if (threadIdx.x < FF) sc[threadIdx.x] = g_c[threadIdx.x];
    __syncthreads();

    float4 c4 = reinterpret_cast<const float4*>(sc)[lane];

    const int rowBase = chunk * 256 + warp * 32;
    float xs0 = 0.f, xs1 = 0.f, xs2 = 0.f, xs3 = 0.f;
    float su = 0.f;

    for (int t = 0; t < 32; t++) {
        const int n = rowBase + t;
        float4 x4 = reinterpret_cast<const float4*>(
                        X + ((long)b * NN + n) * FF)[lane];
        xs0 += x4.x; xs1 += x4.y; xs2 += x4.z; xs3 += x4.w;
        float s = x4.x * c4.x + x4.y * c4.y + x4.z * c4.z + x4.w * c4.w;
#pragma unroll
        for (int off = 16; off; off >>= 1)
            s += __shfl_xor_sync(0xffffffffu, s, off);
        if (lane == t) su = s;     // lane t owns row rowBase+t
    }
    g_u[(long)b * NN + rowBase + lane] = expf(su);

    sx[warp][lane * 4 + 0] = xs0;
    sx[warp][lane * 4 + 1] = xs1;
    sx[warp][lane * 4 + 2] = xs2;
    sx[warp][lane * 4 + 3] = xs3;
    __syncthreads();
    if (threadIdx.x < FF) {
        float v = 0.f;
#pragma unroll
        for (int w2 = 0; w2 < 8; w2++) v += sx[w2][threadIdx.x];
        g_xpart[((long)b * 8 + chunk) * FF + threadIdx.x] = v;  // deterministic
    }
}

// ---------------- k2: S[b,:] = xsum[b,:] @ W  -------------------------------
// grid 8 (batch), block 128
__global__ void k2_S(const float* __restrict__ W)
{
    const int b = blockIdx.x;
    const int t = threadIdx.x;
    __shared__ float xs[FF];
    float v = 0.f;
#pragma unroll
    for (int c = 0; c < 8; c++) v += g_xpart[((long)b * 8 + c) * FF + t];
    xs[t] = v;
    __syncthreads();
    float s = 0.f;
#pragma unroll 8
    for (int fi = 0; fi < FF; fi++) s += xs[fi] * W[fi * FF + t];
    g_S[b * FF + t] = s;
}

// ---------------- k3: w = A @ u  +  bitmask(A != 0)  (THE big scan) ---------
// grid (256, 8), block 256 (8 warps, 1 row per warp)
__global__ void k3_w_bits(const float* __restrict__ A)
{
    const int b = blockIdx.y;
    __shared__ float su[NN];
    for (int i = threadIdx.x; i < NN; i += 256) su[i] = g_u[(long)b * NN + i];
    __syncthreads();

    const int warp = threadIdx.x >> 5;
    const int lane = threadIdx.x & 31;
    const int row  = blockIdx.x * 8 + warp;

    const float* Ar = A + ((long)(b * NN + row)) * NN;
    float acc = 0.f;
    unsigned w0 = 0u, w1 = 0u;
#pragma unroll 8
    for (int j = 0; j < 64; j++) {
        float av = Ar[j * 32 + lane];                 // coalesced 128B
        unsigned bal = __ballot_sync(0xffffffffu, av != 0.f);
        acc += av * su[j * 32 + lane];
        if (j == lane)      w0 = bal;                 // word j kept by lane j
        if (j == lane + 32) w1 = bal;
    }
#pragma unroll
    for (int off = 16; off; off >>= 1)
        acc += __shfl_xor_sync(0xffffffffu, acc, off);

    unsigned* br = g_bits + ((long)(b * NN + row)) * NWRD;
    br[lane]      = w0;
    br[32 + lane] = w1;
    if (lane == 0) g_w[(long)b * NN + row] = acc;
}

// ---------------- k5: q = A @ r (from bitmask); H = q*S + bias_W ------------
// grid (256, 8), block 256 (8 warps, 1 row per warp)
__global__ void k5_out(float* __restrict__ H, const float* __restrict__ biasW)
{
    const int b = blockIdx.y;
    __shared__ float sr[NN];
    __shared__ float sS[FF];
    __shared__ float sbw[FF];
    for (int i = threadIdx.x; i < NN; i += 256) {
        float u = g_u[(long)b * NN + i];
        float w = g_w[(long)b * NN + i];
        sr[i] = (w != 0.f) ? (u / w) : 0.f;   // r, with the num==0 guard
    }
    if (threadIdx.x < FF) {
        sS[threadIdx.x]  = g_S[b * FF + threadIdx.x];
        sbw[threadIdx.x] = biasW[threadIdx.x];
    }
    __syncthreads();

    const int warp = threadIdx.x >> 5;
    const int lane = threadIdx.x & 31;
    const int row  = blockIdx.x * 8 + warp;

    const unsigned* br = g_bits + ((long)(b * NN + row)) * NWRD;
    const unsigned m0 = br[lane];
    const unsigned m1 = br[32 + lane];
    const int base0 = lane * 32;
    const int base1 = (lane + 32) * 32;

    float acc = 0.f;
#pragma unroll
    for (int tt = 0; tt < 32; tt++) {
        const int t = (tt + lane) & 31;       // rotate: bank-conflict-free LDS
        if ((m0 >> t) & 1u) acc += sr[base0 + t];
        if ((m1 >> t) & 1u) acc += sr[base1 + t];
    }
#pragma unroll
    for (int off = 16; off; off >>= 1)
        acc += __shfl_xor_sync(0xffffffffu, acc, off);   // q = A @ r (row)

    float4 s4 = reinterpret_cast<const float4*>(sS)[lane];
    float4 b4 = reinterpret_cast<const float4*>(sbw)[lane];
    float4 o;
    o.x = acc * s4.x + b4.x;
    o.y = acc * s4.y + b4.y;
    o.z = acc * s4.z + b4.z;
    o.w = acc * s4.w + b4.w;
    reinterpret_cast<float4*>(H + ((long)(b * NN + row)) * FF)[lane] = o;
}

// ---------------- launch -----------------------------------------------------
extern "C" void kernel_launch(void* const* d_in, const int* in_sizes, int n_in,
                              void* d_out, int out_size)
{
    const float* X     = (const float*)d_in[0];
    const float* A     = (const float*)d_in[1];
    const float* W     = (const float*)d_in[2];
    const float* a     = (const float*)d_in[3];
    // d_in[4] = bias_a: cancels analytically (rank-1 den), unused.
    const float* biasW = (const float*)d_in[5];
    float* H = (float*)d_out;

    k0_c     <<<1, FF>>>(W, a);
    k1_u_xsum<<<dim3(8, BB), 256>>>(X);
    k2_S     <<<BB, FF>>>(W);
    k3_w_bits<<<dim3(NN / 8, BB), 256>>>(A);
    k5_out   <<<dim3(NN / 8, BB), 256>>>(H, biasW);
}

// round 2
// speedup vs baseline: 1.0842x; 1.0842x over previous
#include <cuda_runtime.h>
#include <math.h>

#define BB 8
#define NN 2048
#define FF 128
#define NWRD (NN / 32)   // 64 bitmask words per row

// ---------------- scratch (device globals; no allocations allowed) ----------
__device__ float    g_c[FF];                  // c = W @ a_i
__device__ float    g_u[BB * NN];             // u = exp(X @ c)
__device__ float    g_w[BB * NN];             // w = A @ u
__device__ float    g_xpart[BB * 128 * FF];   // per-block partial col-sums of X
__device__ float    g_S[BB * FF];             // S = (sum_n X) @ W
__device__ unsigned g_bits[BB * NN * NWRD];   // A != 0 bitmask (4 MB)

// ---------------- k0: c[fi] = sum_o W[fi,o] * a[128+o] ----------------------
__global__ void k0_c(const float* __restrict__ W, const float* __restrict__ a)
{
    __shared__ float sa[FF];
    int t = threadIdx.x;
    sa[t] = a[FF + t];            // a_i = a[0, 128:256]
    __syncthreads();
    const float* wr = W + t * FF;
    float s = 0.f;
#pragma unroll 8
    for (int o = 0; o < FF; o++) s += wr[o] * sa[o];
    g_c[t] = s;
}

// ---------------- k1: u = exp(X @ c); per-block partial column-sums of X ----
// grid (128, 8), block 512 (16 warps, 1 row per warp)
__global__ void k1_u_xsum(const float* __restrict__ X)
{
    const int b    = blockIdx.y;
    const int warp = threadIdx.x >> 5;
    const int lane = threadIdx.x & 31;

    __shared__ float sc[FF];
    __shared__ float sx[16][FF];
    if (threadIdx.x < FF) sc[threadIdx.x] = g_c[threadIdx.x];
    __syncthreads();

    const int row = blockIdx.x * 16 + warp;
    float4 x4 = reinterpret_cast<const float4*>(
                    X + ((size_t)b * NN + row) * FF)[lane];
    float4 c4 = reinterpret_cast<const float4*>(sc)[lane];

    float s = x4.x * c4.x + x4.y * c4.y + x4.z * c4.z + x4.w * c4.w;
#pragma unroll
    for (int off = 16; off; off >>= 1)
        s += __shfl_xor_sync(0xffffffffu, s, off);
    if (lane == 0) g_u[(size_t)b * NN + row] = expf(s);

    reinterpret_cast<float4*>(sx[warp])[lane] = x4;
    __syncthreads();
    if (threadIdx.x < FF) {
        float v = 0.f;
#pragma unroll
        for (int w2 = 0; w2 < 16; w2++) v += sx[w2][threadIdx.x];
        g_xpart[((size_t)b * 128 + blockIdx.x) * FF + threadIdx.x] = v;
    }
}

// ---------------- k2: S[b,:] = xsum[b,:] @ W  -------------------------------
// grid 8 (batch), block 128
__global__ void k2_S(const float* __restrict__ W)
{
    const int b = blockIdx.x;
    const int t = threadIdx.x;
    __shared__ float xs[FF];
    float v = 0.f;
#pragma unroll 8
    for (int c = 0; c < 128; c++) v += g_xpart[((size_t)b * 128 + c) * FF + t];
    xs[t] = v;
    __syncthreads();
    float s = 0.f;
#pragma unroll 8
    for (int fi = 0; fi < FF; fi++) s += xs[fi] * W[fi * FF + t];
    g_S[b * FF + t] = s;
}

// ---------------- k3: w = A @ u  +  bitmask(A != 0)  (THE big scan) ---------
// grid (256, 8), block 256 (8 warps, 1 row per warp). float4 streaming loads.
// Bit layout: word w (0..63): j = w>>2, c = w&3; bit t <-> column j*128+t*4+c
__global__ void k3_w_bits(const float* __restrict__ A)
{
    const int b = blockIdx.y;
    __shared__ float su[NN];
    for (int i = threadIdx.x; i < NN; i += 256) su[i] = g_u[(size_t)b * NN + i];
    __syncthreads();

    const int warp = threadIdx.x >> 5;
    const int lane = threadIdx.x & 31;
    const int row  = blockIdx.x * 8 + warp;

    const float4* Ar = reinterpret_cast<const float4*>(
                           A + ((size_t)(b * NN + row)) * NN);
    const float4* su4 = reinterpret_cast<const float4*>(su);

    const int jmine0 = lane >> 2;        // word lane      -> j = lane>>2
    const int jmine1 = 8 + (lane >> 2);  // word lane+32   -> j = 8+(lane>>2)
    const int c      = lane & 3;

    float ax = 0.f, ay = 0.f, az = 0.f, aw = 0.f;
    unsigned w0 = 0u, w1 = 0u;

#pragma unroll 4
    for (int j = 0; j < 16; j++) {
        float4 av = __ldcs(&Ar[j * 32 + lane]);   // 512B/warp, streaming
        float4 s4 = su4[j * 32 + lane];
        unsigned b0 = __ballot_sync(0xffffffffu, av.x != 0.f);
        unsigned b1 = __ballot_sync(0xffffffffu, av.y != 0.f);
        unsigned b2 = __ballot_sync(0xffffffffu, av.z != 0.f);
        unsigned b3 = __ballot_sync(0xffffffffu, av.w != 0.f);
        ax += av.x * s4.x;
        ay += av.y * s4.y;
        az += av.z * s4.z;
        aw += av.w * s4.w;
        unsigned bs = (c == 0) ? b0 : (c == 1) ? b1 : (c == 2) ? b2 : b3;
        if (j == jmine0) w0 = bs;
        if (j == jmine1) w1 = bs;
    }

    float acc = (ax + ay) + (az + aw);
#pragma unroll
    for (int off = 16; off; off >>= 1)
        acc += __shfl_xor_sync(0xffffffffu, acc, off);

    unsigned* br = g_bits + ((size_t)(b * NN + row)) * NWRD;
    br[lane]      = w0;
    br[32 + lane] = w1;
    if (lane == 0) g_w[(size_t)b * NN + row] = acc;
}

// ---------------- k5: q = A @ r (from bitmask); H = q*S + bias_W ------------
// grid (256, 8), block 256 (8 warps, 1 row per warp)
__global__ void k5_out(float* __restrict__ H, const float* __restrict__ biasW)
{
    const int b = blockIdx.y;
    __shared__ float sr[NN];
    __shared__ float sS[FF];
    __shared__ float sbw[FF];
    for (int i = threadIdx.x; i < NN; i += 256) {
        float u = g_u[(size_t)b * NN + i];
        float w = g_w[(size_t)b * NN + i];
        sr[i] = (w != 0.f) ? (u / w) : 0.f;   // r, with the num==0 guard
    }
    if (threadIdx.x < FF) {
        sS[threadIdx.x]  = g_S[b * FF + threadIdx.x];
        sbw[threadIdx.x] = biasW[threadIdx.x];
    }
    __syncthreads();

    const int warp = threadIdx.x >> 5;
    const int lane = threadIdx.x & 31;
    const int row  = blockIdx.x * 8 + warp;

    const unsigned* br = g_bits + ((size_t)(b * NN + row)) * NWRD;
    const unsigned m0 = br[lane];
    const unsigned m1 = br[32 + lane];

    const int g = lane >> 2;      // j group for word w0; j = g (w1: j = g+8)
    const int c = lane & 3;
    const int base0 = g * 128 + c;          // column = base0 + 4*t
    const int base1 = base0 + 1024;         // (g+8)*128 + c

    float a0 = 0.f, a1 = 0.f, a2 = 0.f, a3 = 0.f;
#pragma unroll
    for (int tt = 0; tt < 16; tt++) {
        const int t0 = (tt + g) & 31;       // stagger: bank-conflict-free
        const int t1 = (tt + 16 + g) & 31;
        if ((m0 >> t0) & 1u) a0 += sr[base0 + t0 * 4];
        if ((m0 >> t1) & 1u) a1 += sr[base0 + t1 * 4];
        if ((m1 >> t0) & 1u) a2 += sr[base1 + t0 * 4];
        if ((m1 >> t1) & 1u) a3 += sr[base1 + t1 * 4];
    }
    float acc = (a0 + a1) + (a2 + a3);
#pragma unroll
    for (int off = 16; off; off >>= 1)
        acc += __shfl_xor_sync(0xffffffffu, acc, off);   // q = (A @ r)[row]

    float4 s4 = reinterpret_cast<const float4*>(sS)[lane];
    float4 b4 = reinterpret_cast<const float4*>(sbw)[lane];
    float4 o;
    o.x = acc * s4.x + b4.x;
    o.y = acc * s4.y + b4.y;
    o.z = acc * s4.z + b4.z;
    o.w = acc * s4.w + b4.w;
    reinterpret_cast<float4*>(H + ((size_t)(b * NN + row)) * FF)[lane] = o;
}

// ---------------- launch -----------------------------------------------------
extern "C" void kernel_launch(void* const* d_in, const int* in_sizes, int n_in,
                              void* d_out, int out_size)
{
    const float* X     = (const float*)d_in[0];
    const float* A     = (const float*)d_in[1];
    const float* W     = (const float*)d_in[2];
    const float* a     = (const float*)d_in[3];
    // d_in[4] = bias_a: cancels analytically (rank-1 den), unused.
    const float* biasW = (const float*)d_in[5];
    float* H = (float*)d_out;

    k0_c     <<<1, FF>>>(W, a);
    k1_u_xsum<<<dim3(128, BB), 512>>>(X);
    k2_S     <<<BB, FF>>>(W);
    k3_w_bits<<<dim3(NN / 8, BB), 256>>>(A);
    k5_out   <<<dim3(NN / 8, BB), 256>>>(H, biasW);
}

// round 3
// speedup vs baseline: 1.5338x; 1.4147x over previous
#include <cuda_runtime.h>
#include <math.h>

#define BB 8
#define NN 2048
#define FF 128
#define NWRD (NN / 32)   // 64 bitmask words per row

// ---------------- scratch (device globals; no allocations allowed) ----------
__device__ float    g_c[FF];                  // c = W @ a_i
__device__ float    g_u[BB * NN];             // u = exp(X @ c)
__device__ float    g_w[BB * NN];             // w = A @ u
__device__ float    g_xpart[BB * 128 * FF];   // per-block partial col-sums of X
__device__ float    g_S[BB * FF];             // S = (sum_n X) @ W
__device__ unsigned g_bits[BB * NN * NWRD];   // A != 0 bitmask (4 MB)

// ---------------- k0: c[fi] = sum_o W[fi,o] * a[128+o]  (warp per fi) -------
// grid 4, block 1024 -> 128 warps, one output each
__global__ void k0_c(const float* __restrict__ W, const float* __restrict__ a)
{
    const int warp = (blockIdx.x * 1024 + threadIdx.x) >> 5;  // = fi
    const int lane = threadIdx.x & 31;

    float4 w4 = reinterpret_cast<const float4*>(W + warp * FF)[lane];
    float4 a4 = reinterpret_cast<const float4*>(a + FF)[lane];   // a_i
    float s = w4.x * a4.x + w4.y * a4.y + w4.z * a4.z + w4.w * a4.w;
#pragma unroll
    for (int off = 16; off; off >>= 1)
        s += __shfl_xor_sync(0xffffffffu, s, off);
    if (lane == 0) g_c[warp] = s;
}

// ---------------- k1: u = exp(X @ c); per-block partial column-sums of X ----
// grid (128, 8), block 512 (16 warps, 1 row per warp)
__global__ void k1_u_xsum(const float* __restrict__ X)
{
    const int b    = blockIdx.y;
    const int warp = threadIdx.x >> 5;
    const int lane = threadIdx.x & 31;

    __shared__ float sc[FF];
    __shared__ float sx[16][FF];
    if (threadIdx.x < FF) sc[threadIdx.x] = g_c[threadIdx.x];
    __syncthreads();

    const int row = blockIdx.x * 16 + warp;
    float4 x4 = reinterpret_cast<const float4*>(
                    X + ((size_t)b * NN + row) * FF)[lane];
    float4 c4 = reinterpret_cast<const float4*>(sc)[lane];

    float s = x4.x * c4.x + x4.y * c4.y + x4.z * c4.z + x4.w * c4.w;
#pragma unroll
    for (int off = 16; off; off >>= 1)
        s += __shfl_xor_sync(0xffffffffu, s, off);
    if (lane == 0) g_u[(size_t)b * NN + row] = expf(s);

    reinterpret_cast<float4*>(sx[warp])[lane] = x4;
    __syncthreads();
    if (threadIdx.x < FF) {
        float v = 0.f;
#pragma unroll
        for (int w2 = 0; w2 < 16; w2++) v += sx[w2][threadIdx.x];
        g_xpart[((size_t)b * 128 + blockIdx.x) * FF + threadIdx.x] = v;
    }
}

// ---------------- k3: w = A @ u + bitmask(A != 0) + (fused) S ---------------
// grid (129, 8), block 512. Blocks 0..127: 16 rows each, 8-deep prefetch.
// Block 128: computes S[b,:] = (col-sums of X) @ W in parallel with the scan.
// Bit layout: word w (0..63): j = w>>2, c = w&3; bit t <-> column j*128+t*4+c
__global__ void __launch_bounds__(512) k3_w_bits_S(const float* __restrict__ A,
                                                   const float* __restrict__ W)
{
    const int b = blockIdx.y;

    if (blockIdx.x == 128) {
        // ---- S path: xs = sum over 128 chunks of g_xpart; S = xs @ W ----
        __shared__ float part[4][FF];
        __shared__ float xs[FF];
        __shared__ float dot[4][FF];
        const int t = threadIdx.x & 127;
        const int p = threadIdx.x >> 7;          // 0..3
        float v = 0.f;
#pragma unroll 8
        for (int c = 0; c < 32; c++)
            v += g_xpart[((size_t)b * 128 + p * 32 + c) * FF + t];
        part[p][t] = v;
        __syncthreads();
        if (threadIdx.x < FF)
            xs[t] = part[0][t] + part[1][t] + part[2][t] + part[3][t];
        __syncthreads();
        float s = 0.f;
#pragma unroll 8
        for (int k = 0; k < 32; k++) {
            const int fi = p * 32 + k;
            s += xs[fi] * W[fi * FF + t];
        }
        dot[p][t] = s;
        __syncthreads();
        if (threadIdx.x < FF)
            g_S[b * FF + t] = dot[0][t] + dot[1][t] + dot[2][t] + dot[3][t];
        return;
    }

    __shared__ float su[NN];
    for (int i = threadIdx.x; i < NN; i += 512) su[i] = g_u[(size_t)b * NN + i];
    __syncthreads();

    const int warp = threadIdx.x >> 5;
    const int lane = threadIdx.x & 31;
    const int row  = blockIdx.x * 16 + warp;

    const float4* Ar = reinterpret_cast<const float4*>(
                           A + ((size_t)(b * NN + row)) * NN);
    const float4* su4 = reinterpret_cast<const float4*>(su);

    const int jmine0 = lane >> 2;        // word lane      -> j = lane>>2
    const int jmine1 = 8 + (lane >> 2);  // word lane+32   -> j = 8+(lane>>2)
    const int c      = lane & 3;

    float ax = 0.f, ay = 0.f, az = 0.f, aw = 0.f;
    unsigned w0 = 0u, w1 = 0u;

#pragma unroll
    for (int half = 0; half < 2; half++) {
        float4 v[8];
#pragma unroll
        for (int k = 0; k < 8; k++)          // 8 LDG.128 in flight per warp
            v[k] = __ldcs(&Ar[(half * 8 + k) * 32 + lane]);
#pragma unroll
        for (int k = 0; k < 8; k++) {
            const int j = half * 8 + k;
            float4 s4 = su4[j * 32 + lane];
            unsigned b0 = __ballot_sync(0xffffffffu, v[k].x != 0.f);
            unsigned b1 = __ballot_sync(0xffffffffu, v[k].y != 0.f);
            unsigned b2 = __ballot_sync(0xffffffffu, v[k].z != 0.f);
            unsigned b3 = __ballot_sync(0xffffffffu, v[k].w != 0.f);
            ax += v[k].x * s4.x;
            ay += v[k].y * s4.y;
            az += v[k].z * s4.z;
            aw += v[k].w * s4.w;
            unsigned bs = (c == 0) ? b0 : (c == 1) ? b1 : (c == 2) ? b2 : b3;
            if (j == jmine0) w0 = bs;
            if (j == jmine1) w1 = bs;
        }
    }

    float acc = (ax + ay) + (az + aw);
#pragma unroll
    for (int off = 16; off; off >>= 1)
        acc += __shfl_xor_sync(0xffffffffu, acc, off);

    unsigned* br = g_bits + ((size_t)(b * NN + row)) * NWRD;
    br[lane]      = w0;
    br[32 + lane] = w1;
    if (lane == 0) g_w[(size_t)b * NN + row] = acc;
}

// ---------------- k5: q = A @ r (from bitmask); H = q*S + bias_W ------------
// grid (128, 8), block 512 (16 warps, 1 row per warp)
__global__ void k5_out(float* __restrict__ H, const float* __restrict__ biasW)
{
    const int b = blockIdx.y;
    __shared__ float sr[NN];
    __shared__ float sS[FF];
    __shared__ float sbw[FF];
    for (int i = threadIdx.x; i < NN; i += 512) {
        float u = g_u[(size_t)b * NN + i];
        float w = g_w[(size_t)b * NN + i];
        sr[i] = (w != 0.f) ? __fdividef(u, w) : 0.f;  // r, num==0 guard
    }
    if (threadIdx.x < FF) {
        sS[threadIdx.x]  = g_S[b * FF + threadIdx.x];
        sbw[threadIdx.x] = biasW[threadIdx.x];
    }
    __syncthreads();

    const int warp = threadIdx.x >> 5;
    const int lane = threadIdx.x & 31;
    const int row  = blockIdx.x * 16 + warp;

    const unsigned* br = g_bits + ((size_t)(b * NN + row)) * NWRD;
    const unsigned m0 = br[lane];
    const unsigned m1 = br[32 + lane];

    const int g = lane >> 2;      // j group for word w0; j = g (w1: j = g+8)
    const int c = lane & 3;
    const int base0 = g * 128 + c;          // column = base0 + 4*t
    const int base1 = base0 + 1024;         // (g+8)*128 + c

    float a0 = 0.f, a1 = 0.f, a2 = 0.f, a3 = 0.f;
#pragma unroll
    for (int tt = 0; tt < 16; tt++) {
        const int t0 = (tt + g) & 31;       // stagger: bank-conflict-free
        const int t1 = (tt + 16 + g) & 31;
        if ((m0 >> t0) & 1u) a0 += sr[base0 + t0 * 4];
        if ((m0 >> t1) & 1u) a1 += sr[base0 + t1 * 4];
        if ((m1 >> t0) & 1u) a2 += sr[base1 + t0 * 4];
        if ((m1 >> t1) & 1u) a3 += sr[base1 + t1 * 4];
    }
    float acc = (a0 + a1) + (a2 + a3);
#pragma unroll
    for (int off = 16; off; off >>= 1)
        acc += __shfl_xor_sync(0xffffffffu, acc, off);   // q = (A @ r)[row]

    float4 s4 = reinterpret_cast<const float4*>(sS)[lane];
    float4 b4 = reinterpret_cast<const float4*>(sbw)[lane];
    float4 o;
    o.x = acc * s4.x + b4.x;
    o.y = acc * s4.y + b4.y;
    o.z = acc * s4.z + b4.z;
    o.w = acc * s4.w + b4.w;
    reinterpret_cast<float4*>(H + ((size_t)(b * NN + row)) * FF)[lane] = o;
}

// ---------------- launch -----------------------------------------------------
extern "C" void kernel_launch(void* const* d_in, const int* in_sizes, int n_in,
                              void* d_out, int out_size)
{
    const float* X     = (const float*)d_in[0];
    const float* A     = (const float*)d_in[1];
    const float* W     = (const float*)d_in[2];
    const float* a     = (const float*)d_in[3];
    // d_in[4] = bias_a: cancels analytically (rank-1 den), unused.
    const float* biasW = (const float*)d_in[5];
    float* H = (float*)d_out;

    k0_c       <<<4, 1024>>>(W, a);
    k1_u_xsum  <<<dim3(128, BB), 512>>>(X);
    k3_w_bits_S<<<dim3(129, BB), 512>>>(A, W);
    k5_out     <<<dim3(128, BB), 512>>>(H, biasW);
}